// round 4
// baseline (speedup 1.0000x reference)
#include <cuda_runtime.h>
#include <math.h>
#include <stdint.h>

// ---------------- problem constants ----------------
#define NWIN 200
#define WINL 160
#define HOPL 80
#define INPD 40
#define HID  768
#define G4   3072
#define NB   128          // persistent blocks (1 per SM, all co-resident)
#define NT   256          // threads per block
#define KMAX 1536         // max fused K (HID + HID)
#define CPB  6            // hidden units per block (128*6 = 768)
#define NC   24           // gate columns per block (4 gates * 6 units)
#define AST  202          // a_s smem row stride (even -> u64 aligned, 2-way bank max)

// ---------------- persistent device scratch ----------------
__device__ float g_hA[NWIN * HID];
__device__ float g_hB[NWIN * HID];
__device__ float g_hs0[NWIN * WINL * HID];   // layer0 output sequence
__device__ float g_hs1[NWIN * WINL * HID];   // layer1 output sequence
__device__ float g_y[NWIN * 256];
__device__ unsigned g_barcnt = 0;
__device__ unsigned g_bargen = 0;

struct P {
    const float *x;
    const float *wih0, *whh0, *bih0, *bhh0;
    const float *wih1, *whh1, *bih1, *bhh1;
    const float *wih2, *whh2, *bih2, *bhh2;
};

// ---------------- software grid barrier ----------------
__device__ __forceinline__ void grid_bar() {
    __syncthreads();
    if (threadIdx.x == 0) {
        unsigned g = atomicAdd(&g_bargen, 0u);   // read current generation (L2-coherent)
        __threadfence();                          // release my writes
        unsigned old = atomicAdd(&g_barcnt, 1u);
        if (old == gridDim.x - 1) {
            g_barcnt = 0;
            __threadfence();
            atomicAdd(&g_bargen, 1u);
        } else {
            while (atomicAdd(&g_bargen, 0u) == g) __nanosleep(64);
        }
        __threadfence();                          // acquire others' writes
    }
    __syncthreads();
}

// ---------------- fast activations (overflow-safe) ----------------
__device__ __forceinline__ float sigf(float v) {
    return 1.f / (1.f + __expf(-v));
}
__device__ __forceinline__ float tanhfast(float x) {
    float ax = fabsf(x);
    float e = __expf(-2.f * ax);
    float t = (1.f - e) / (1.f + e);
    return copysignf(t, x);
}

// ---------------- packed f32x2 helpers ----------------
#define FMA2(acc, a, w) \
    asm("fma.rn.f32x2 %0, %1, %2, %0;" : "+l"(acc) : "l"(a), "l"(w))
#define PACK2(dst, lo, hi) \
    asm("mov.b64 %0, {%1, %2};" : "=l"(dst) : "r"(lo), "r"(hi))
#define UNPACK2(lo, hi, src) \
    asm("mov.b64 {%0, %1}, %2;" : "=r"(lo), "=r"(hi) : "l"(src))

// ============================================================
// Persistent kernel: the full 3-layer, 160-step LSTM recurrence
// ============================================================
__global__ void __launch_bounds__(NT, 1) lstm_all(P p)
{
    extern __shared__ float sm[];
    float* w_s = sm;                     // [KMAX][NC]  = 36864 floats (147 KB)
    float* a_s = w_s + KMAX * NC;        // [32][AST]   = 6464 floats (A tile; aliased as gates[200][24])
    float* c_s = a_s + 32 * AST;         // [200*6]     = 1200 floats (cell state, block-local)
    float* b_s = c_s + NWIN * CPB;       // [24] bias

    const int tid = threadIdx.x;
    const int bid = blockIdx.x;
    const int u0  = bid * CPB;            // first hidden unit owned by this block
    const int tm  = tid >> 3;             // 0..24 (for tid<200)
    const int tc  = tid & 7;              // 0..7
    const int m0  = tm * 8;               // 8 batch rows per thread
    const int c0  = tc * 3;               // 3 gate cols per thread
    const bool comp = (tid < 200);

    const float* wih[3] = { p.wih0, p.wih1, p.wih2 };
    const float* whh[3] = { p.whh0, p.whh1, p.whh2 };
    const float* bih[3] = { p.bih0, p.bih1, p.bih2 };
    const float* bhh[3] = { p.bhh0, p.bhh1, p.bhh2 };

    for (int l = 0; l < 3; l++) {
        const int in_dim = (l == 0) ? INPD : HID;
        const int Ktot   = HID + in_dim;
        const int nch    = (Ktot + 31) >> 5;           // 26 or 48
        const float* xin = (l == 1) ? g_hs0 : g_hs1;   // layer>=1 input sequence
        float* hsout = (l == 0) ? g_hs0 : ((l == 1) ? g_hs1 : nullptr);

        // ---- load this block's weight slice into smem: w_s[k][c] ----
        for (int idx = tid; idx < NC * KMAX; idx += NT) {
            int c = idx / KMAX, k = idx - c * KMAX;
            int g = c / CPB, u = c - g * CPB;
            int row = g * HID + u0 + u;                // global gate column
            float v = 0.f;
            if (k < HID) v = whh[l][row * HID + k];
            else { int kk = k - HID; if (kk < in_dim) v = wih[l][row * in_dim + kk]; }
            w_s[k * NC + c] = v;
        }
        if (tid < NC) {
            int g = tid / CPB, u = tid - g * CPB;
            int col = g * HID + u0 + u;
            b_s[tid] = bih[l][col] + bhh[l][col];
        }
        for (int i = tid; i < NWIN * CPB; i += NT) c_s[i] = 0.f;
        // zero h read buffer (each block zeroes a disjoint 1200-float slice; 128*1200 = 153600)
        for (int i = tid; i < 1200; i += NT) g_hA[bid * 1200 + i] = 0.f;
        grid_bar();

        for (int t = 0; t < WINL; t++) {
            const float* hcur = (t & 1) ? g_hB : g_hA;
            float*       hnxt = (t & 1) ? g_hA : g_hB;

            // accumulators: 4 row-pairs x 3 cols, packed f32x2, init with bias
            unsigned long long acc[4][3];
            if (comp) {
#pragma unroll
                for (int c = 0; c < 3; c++) {
                    unsigned bbits = __float_as_uint(b_s[c0 + c]);
                    unsigned long long bb; PACK2(bb, bbits, bbits);
#pragma unroll
                    for (int pr = 0; pr < 4; pr++) acc[pr][c] = bb;
                }
            }

            for (int ch = 0; ch < nch; ch++) {
                const int k0 = ch << 5;
                __syncthreads();   // a_s free to overwrite
                // ---- stage A tile: a_s[j][m] for j=0..31, m=0..199 ----
                if (k0 < HID) {
                    // pure h chunk: float4 loads, L2-coherent
                    for (int i4 = tid; i4 < 1600; i4 += NT) {
                        int m = i4 >> 3, q = i4 & 7;
                        const float4* src = (const float4*)&hcur[m * HID + k0 + q * 4];
                        float4 v; v.x = __ldcg(&src->x); // load float4 via ldcg on components
                        // better: single vector cg load
                        v = __ldcg(src);
                        int jb = q * 4;
                        a_s[(jb    ) * AST + m] = v.x;
                        a_s[(jb + 1) * AST + m] = v.y;
                        a_s[(jb + 2) * AST + m] = v.z;
                        a_s[(jb + 3) * AST + m] = v.w;
                    }
                } else if (l > 0) {
                    // pure x chunk, layer>=1: full 768-wide rows, float4 safe
                    const int kk0b = k0 - HID;
                    for (int i4 = tid; i4 < 1600; i4 += NT) {
                        int m = i4 >> 3, q = i4 & 7;
                        float4 v = __ldcg((const float4*)&xin[(m * WINL + t) * HID + kk0b + q * 4]);
                        int jb = q * 4;
                        a_s[(jb    ) * AST + m] = v.x;
                        a_s[(jb + 1) * AST + m] = v.y;
                        a_s[(jb + 2) * AST + m] = v.z;
                        a_s[(jb + 3) * AST + m] = v.w;
                    }
                } else {
                    // layer0 x chunk (in_dim=40): scalar with bounds guard
                    for (int idx = tid; idx < 6400; idx += NT) {
                        int m = (tid >> 5) + (idx - tid) / 32;  // m = idx/32
                        int j = tid & 31;                        // j = idx%32
                        int kk = k0 + j - HID;
                        float v = (kk < INPD) ? __ldcg(&p.x[(m * HOPL + t) * INPD + kk]) : 0.f;
                        a_s[j * AST + m] = v;
                    }
                }
                __syncthreads();
                // ---- compute: 32 k-steps, packed f32x2 FMAs ----
                if (comp) {
#pragma unroll 8
                    for (int kk = 0; kk < 32; kk++) {
                        const unsigned long long* ap =
                            (const unsigned long long*)&a_s[kk * AST + m0];
                        unsigned long long a0 = ap[0], a1 = ap[1], a2 = ap[2], a3 = ap[3];
                        const float* wr = &w_s[(k0 + kk) * NC + c0];
#pragma unroll
                        for (int c = 0; c < 3; c++) {
                            unsigned wb = __float_as_uint(wr[c]);
                            unsigned long long wp; PACK2(wp, wb, wb);
                            FMA2(acc[0][c], a0, wp);
                            FMA2(acc[1][c], a1, wp);
                            FMA2(acc[2][c], a2, wp);
                            FMA2(acc[3][c], a3, wp);
                        }
                    }
                }
            }

            __syncthreads();
            // ---- spill gates to smem (alias a_s as gates[200][24]) ----
            if (comp) {
#pragma unroll
                for (int pr = 0; pr < 4; pr++) {
#pragma unroll
                    for (int c = 0; c < 3; c++) {
                        unsigned lo, hi; UNPACK2(lo, hi, acc[pr][c]);
                        a_s[(m0 + 2 * pr    ) * NC + c0 + c] = __uint_as_float(lo);
                        a_s[(m0 + 2 * pr + 1) * NC + c0 + c] = __uint_as_float(hi);
                    }
                }
            }
            __syncthreads();
            // ---- cell update for this block's 6 units x 200 rows ----
            for (int i = tid; i < NWIN * CPB; i += NT) {
                int m = i / CPB, u = i - m * CPB;
                float gi = a_s[m * NC +      u];
                float gf = a_s[m * NC +  6 + u];
                float gg = a_s[m * NC + 12 + u];
                float go = a_s[m * NC + 18 + u];
                float c = c_s[i];
                c = sigf(gf) * c + sigf(gi) * tanhfast(gg);
                float h = sigf(go) * tanhfast(c);
                c_s[i] = c;
                hnxt[m * HID + u0 + u] = h;
                if (hsout) hsout[(m * WINL + t) * HID + u0 + u] = h;
            }
            grid_bar();
        }
        // after 160 steps (even), final h of this layer sits in g_hA
    }
}

// ---------------- output projection + row normalize ----------------
__global__ void out_proj_kernel(const float* __restrict__ w_out,
                                const float* __restrict__ b_out)
{
    __shared__ float red[256];
    int b = blockIdx.x;
    int o = threadIdx.x;
    const float4* h = (const float4*)(g_hA + (long)b * HID);
    const float4* w = (const float4*)(w_out + (long)o * HID);
    float s = 0.f;
#pragma unroll 4
    for (int k = 0; k < HID / 4; k++) {
        float4 hv = h[k];
        float4 wv = w[k];
        s += hv.x * wv.x + hv.y * wv.y + hv.z * wv.z + hv.w * wv.w;
    }
    float y = s + b_out[o];
    red[o] = y * y;
    __syncthreads();
    for (int st = 128; st > 0; st >>= 1) {
        if (o < st) red[o] += red[o + st];
        __syncthreads();
    }
    float inv = rsqrtf(red[0]);
    g_y[b * 256 + o] = y * inv;
}

__global__ void mean_kernel(float* __restrict__ out) {
    int o = threadIdx.x;
    float s = 0.f;
    for (int b = 0; b < NWIN; b++) s += g_y[b * 256 + o];
    out[o] = s / (float)NWIN;
}

// ---------------- launch ----------------
extern "C" void kernel_launch(void* const* d_in, const int* in_sizes, int n_in,
                              void* d_out, int out_size)
{
    (void)in_sizes; (void)n_in; (void)out_size;
    P p;
    p.x    = (const float*)d_in[0];
    p.wih0 = (const float*)d_in[1];  p.whh0 = (const float*)d_in[2];
    p.bih0 = (const float*)d_in[3];  p.bhh0 = (const float*)d_in[4];
    p.wih1 = (const float*)d_in[5];  p.whh1 = (const float*)d_in[6];
    p.bih1 = (const float*)d_in[7];  p.bhh1 = (const float*)d_in[8];
    p.wih2 = (const float*)d_in[9];  p.whh2 = (const float*)d_in[10];
    p.bih2 = (const float*)d_in[11]; p.bhh2 = (const float*)d_in[12];
    const float* w_out = (const float*)d_in[13];
    const float* b_out = (const float*)d_in[14];
    float* out = (float*)d_out;

    const size_t smem_bytes =
        (size_t)(KMAX * NC + 32 * AST + NWIN * CPB + 32) * sizeof(float);  // ~178 KB

    cudaFuncSetAttribute(lstm_all, cudaFuncAttributeMaxDynamicSharedMemorySize,
                         (int)smem_bytes);

    lstm_all<<<NB, NT, smem_bytes>>>(p);
    out_proj_kernel<<<NWIN, 256>>>(w_out, b_out);
    mean_kernel<<<1, 256>>>(out);
}

// round 5
// speedup vs baseline: 1.3740x; 1.3740x over previous
#include <cuda_runtime.h>
#include <math.h>
#include <stdint.h>

// ---------------- problem constants ----------------
#define NWIN 200
#define WINL 160
#define HOPL 80
#define INPD 40
#define HID  768
#define G4   3072
#define NB   128          // persistent blocks (1 per SM, all co-resident)
#define NT   256          // threads per block
#define KMAX 1536         // max fused K (HID + HID)
#define CPB  6            // hidden units per block (128*6 = 768)
#define NC   24           // gate columns per block (4 gates * 6 units)
#define AST  202          // a_s smem row stride (even -> u64 aligned, 2-way bank max)

// ---------------- persistent device scratch ----------------
__device__ float g_hA[NWIN * HID];
__device__ float g_hB[NWIN * HID];
__device__ float g_hs0[NWIN * WINL * HID];   // layer0 output sequence
__device__ float g_hs1[NWIN * WINL * HID];   // layer1 output sequence
__device__ float g_y[NWIN * 256];
__device__ unsigned g_barcnt = 0;
__device__ unsigned g_bargen = 0;

struct P {
    const float *x;
    const float *wih0, *whh0, *bih0, *bhh0;
    const float *wih1, *whh1, *bih1, *bhh1;
    const float *wih2, *whh2, *bih2, *bhh2;
};

// ---------------- software grid barrier ----------------
__device__ __forceinline__ void grid_bar() {
    __syncthreads();
    if (threadIdx.x == 0) {
        unsigned g = atomicAdd(&g_bargen, 0u);   // read current generation (L2-coherent)
        __threadfence();                          // release my writes
        unsigned old = atomicAdd(&g_barcnt, 1u);
        if (old == gridDim.x - 1) {
            g_barcnt = 0;
            __threadfence();
            atomicAdd(&g_bargen, 1u);
        } else {
            while (atomicAdd(&g_bargen, 0u) == g) __nanosleep(64);
        }
        __threadfence();                          // acquire others' writes
    }
    __syncthreads();
}

// ---------------- fast activations (overflow-safe) ----------------
__device__ __forceinline__ float sigf(float v) {
    return 1.f / (1.f + __expf(-v));
}
__device__ __forceinline__ float tanhfast(float x) {
    float ax = fabsf(x);
    float e = __expf(-2.f * ax);
    float t = (1.f - e) / (1.f + e);
    return copysignf(t, x);
}

// ---------------- packed f32x2 helpers ----------------
#define FMA2(acc, a, w) \
    asm("fma.rn.f32x2 %0, %1, %2, %0;" : "+l"(acc) : "l"(a), "l"(w))
#define PACK2(dst, lo, hi) \
    asm("mov.b64 %0, {%1, %2};" : "=l"(dst) : "r"(lo), "r"(hi))
#define UNPACK2(lo, hi, src) \
    asm("mov.b64 {%0, %1}, %2;" : "=r"(lo), "=r"(hi) : "l"(src))

// ============================================================
// Persistent kernel: the full 3-layer, 160-step LSTM recurrence
// ============================================================
__global__ void __launch_bounds__(NT, 1) lstm_all(P p)
{
    extern __shared__ float sm[];
    float* w_s = sm;                     // [KMAX][NC]  = 36864 floats (147 KB)
    float* a_s = w_s + KMAX * NC;        // [32][AST]   = 6464 floats (A tile; aliased as gates[200][24])
    float* c_s = a_s + 32 * AST;         // [200*6]     = 1200 floats (cell state, block-local)
    float* b_s = c_s + NWIN * CPB;       // [24] bias

    const int tid = threadIdx.x;
    const int bid = blockIdx.x;
    const int u0  = bid * CPB;            // first hidden unit owned by this block
    const int tm  = tid >> 3;             // 0..24 (for tid<200)
    const int tc  = tid & 7;              // 0..7
    const int m0  = tm * 8;               // 8 batch rows per thread
    const int c0  = tc * 3;               // 3 gate cols per thread
    const bool comp = (tid < 200);

    const float* wih[3] = { p.wih0, p.wih1, p.wih2 };
    const float* whh[3] = { p.whh0, p.whh1, p.whh2 };
    const float* bih[3] = { p.bih0, p.bih1, p.bih2 };
    const float* bhh[3] = { p.bhh0, p.bhh1, p.bhh2 };

    for (int l = 0; l < 3; l++) {
        const int in_dim = (l == 0) ? INPD : HID;
        const int Ktot   = HID + in_dim;
        const int nch    = (Ktot + 31) >> 5;           // 26 or 48
        const float* xin = (l == 1) ? g_hs0 : g_hs1;   // layer>=1 input sequence
        float* hsout = (l == 0) ? g_hs0 : ((l == 1) ? g_hs1 : nullptr);

        // ---- load this block's weight slice into smem: w_s[k][c] ----
        for (int idx = tid; idx < NC * KMAX; idx += NT) {
            int c = idx / KMAX, k = idx - c * KMAX;
            int g = c / CPB, u = c - g * CPB;
            int row = g * HID + u0 + u;                // global gate column
            float v = 0.f;
            if (k < HID) v = whh[l][row * HID + k];
            else { int kk = k - HID; if (kk < in_dim) v = wih[l][row * in_dim + kk]; }
            w_s[k * NC + c] = v;
        }
        if (tid < NC) {
            int g = tid / CPB, u = tid - g * CPB;
            int col = g * HID + u0 + u;
            b_s[tid] = bih[l][col] + bhh[l][col];
        }
        for (int i = tid; i < NWIN * CPB; i += NT) c_s[i] = 0.f;
        // zero h read buffer (each block zeroes a disjoint 1200-float slice; 128*1200 = 153600)
        for (int i = tid; i < 1200; i += NT) g_hA[bid * 1200 + i] = 0.f;
        grid_bar();

        for (int t = 0; t < WINL; t++) {
            const float* hcur = (t & 1) ? g_hB : g_hA;
            float*       hnxt = (t & 1) ? g_hA : g_hB;

            // accumulators: 4 row-pairs x 3 cols, packed f32x2, init with bias
            unsigned long long acc[4][3];
            if (comp) {
#pragma unroll
                for (int c = 0; c < 3; c++) {
                    unsigned bbits = __float_as_uint(b_s[c0 + c]);
                    unsigned long long bb; PACK2(bb, bbits, bbits);
#pragma unroll
                    for (int pr = 0; pr < 4; pr++) acc[pr][c] = bb;
                }
            }

            for (int ch = 0; ch < nch; ch++) {
                const int k0 = ch << 5;
                __syncthreads();   // a_s free to overwrite
                // ---- stage A tile: a_s[j][m] for j=0..31, m=0..199 ----
                if (k0 < HID) {
                    // pure h chunk: float4 loads, L2-coherent
                    for (int i4 = tid; i4 < 1600; i4 += NT) {
                        int m = i4 >> 3, q = i4 & 7;
                        const float4* src = (const float4*)&hcur[m * HID + k0 + q * 4];
                        float4 v; v.x = __ldcg(&src->x); // load float4 via ldcg on components
                        // better: single vector cg load
                        v = __ldcg(src);
                        int jb = q * 4;
                        a_s[(jb    ) * AST + m] = v.x;
                        a_s[(jb + 1) * AST + m] = v.y;
                        a_s[(jb + 2) * AST + m] = v.z;
                        a_s[(jb + 3) * AST + m] = v.w;
                    }
                } else if (l > 0) {
                    // pure x chunk, layer>=1: full 768-wide rows, float4 safe
                    const int kk0b = k0 - HID;
                    for (int i4 = tid; i4 < 1600; i4 += NT) {
                        int m = i4 >> 3, q = i4 & 7;
                        float4 v = __ldcg((const float4*)&xin[(m * WINL + t) * HID + kk0b + q * 4]);
                        int jb = q * 4;
                        a_s[(jb    ) * AST + m] = v.x;
                        a_s[(jb + 1) * AST + m] = v.y;
                        a_s[(jb + 2) * AST + m] = v.z;
                        a_s[(jb + 3) * AST + m] = v.w;
                    }
                } else {
                    // layer0 x chunk (in_dim=40): scalar with bounds guard
                    for (int idx = tid; idx < 6400; idx += NT) {
                        int m = (tid >> 5) + (idx - tid) / 32;  // m = idx/32
                        int j = tid & 31;                        // j = idx%32
                        int kk = k0 + j - HID;
                        float v = (kk < INPD) ? __ldcg(&p.x[(m * HOPL + t) * INPD + kk]) : 0.f;
                        a_s[j * AST + m] = v;
                    }
                }
                __syncthreads();
                // ---- compute: 32 k-steps, packed f32x2 FMAs ----
                if (comp) {
#pragma unroll 8
                    for (int kk = 0; kk < 32; kk++) {
                        const unsigned long long* ap =
                            (const unsigned long long*)&a_s[kk * AST + m0];
                        unsigned long long a0 = ap[0], a1 = ap[1], a2 = ap[2], a3 = ap[3];
                        const float* wr = &w_s[(k0 + kk) * NC + c0];
#pragma unroll
                        for (int c = 0; c < 3; c++) {
                            unsigned wb = __float_as_uint(wr[c]);
                            unsigned long long wp; PACK2(wp, wb, wb);
                            FMA2(acc[0][c], a0, wp);
                            FMA2(acc[1][c], a1, wp);
                            FMA2(acc[2][c], a2, wp);
                            FMA2(acc[3][c], a3, wp);
                        }
                    }
                }
            }

            __syncthreads();
            // ---- spill gates to smem (alias a_s as gates[200][24]) ----
            if (comp) {
#pragma unroll
                for (int pr = 0; pr < 4; pr++) {
#pragma unroll
                    for (int c = 0; c < 3; c++) {
                        unsigned lo, hi; UNPACK2(lo, hi, acc[pr][c]);
                        a_s[(m0 + 2 * pr    ) * NC + c0 + c] = __uint_as_float(lo);
                        a_s[(m0 + 2 * pr + 1) * NC + c0 + c] = __uint_as_float(hi);
                    }
                }
            }
            __syncthreads();
            // ---- cell update for this block's 6 units x 200 rows ----
            for (int i = tid; i < NWIN * CPB; i += NT) {
                int m = i / CPB, u = i - m * CPB;
                float gi = a_s[m * NC +      u];
                float gf = a_s[m * NC +  6 + u];
                float gg = a_s[m * NC + 12 + u];
                float go = a_s[m * NC + 18 + u];
                float c = c_s[i];
                c = sigf(gf) * c + sigf(gi) * tanhfast(gg);
                float h = sigf(go) * tanhfast(c);
                c_s[i] = c;
                hnxt[m * HID + u0 + u] = h;
                if (hsout) hsout[(m * WINL + t) * HID + u0 + u] = h;
            }
            grid_bar();
        }
        // after 160 steps (even), final h of this layer sits in g_hA
    }
}

// ---------------- output projection + row normalize ----------------
__global__ void out_proj_kernel(const float* __restrict__ w_out,
                                const float* __restrict__ b_out)
{
    __shared__ float red[256];
    int b = blockIdx.x;
    int o = threadIdx.x;
    const float4* h = (const float4*)(g_hA + (long)b * HID);
    const float4* w = (const float4*)(w_out + (long)o * HID);
    float s = 0.f;
#pragma unroll 4
    for (int k = 0; k < HID / 4; k++) {
        float4 hv = h[k];
        float4 wv = w[k];
        s += hv.x * wv.x + hv.y * wv.y + hv.z * wv.z + hv.w * wv.w;
    }
    float y = s + b_out[o];
    red[o] = y * y;
    __syncthreads();
    for (int st = 128; st > 0; st >>= 1) {
        if (o < st) red[o] += red[o + st];
        __syncthreads();
    }
    float inv = rsqrtf(red[0]);
    g_y[b * 256 + o] = y * inv;
}

__global__ void mean_kernel(float* __restrict__ out) {
    int o = threadIdx.x;
    float s = 0.f;
    for (int b = 0; b < NWIN; b++) s += g_y[b * 256 + o];
    out[o] = s / (float)NWIN;
}

// ---------------- launch ----------------
extern "C" void kernel_launch(void* const* d_in, const int* in_sizes, int n_in,
                              void* d_out, int out_size)
{
    (void)in_sizes; (void)n_in; (void)out_size;
    P p;
    p.x    = (const float*)d_in[0];
    p.wih0 = (const float*)d_in[1];  p.whh0 = (const float*)d_in[2];
    p.bih0 = (const float*)d_in[3];  p.bhh0 = (const float*)d_in[4];
    p.wih1 = (const float*)d_in[5];  p.whh1 = (const float*)d_in[6];
    p.bih1 = (const float*)d_in[7];  p.bhh1 = (const float*)d_in[8];
    p.wih2 = (const float*)d_in[9];  p.whh2 = (const float*)d_in[10];
    p.bih2 = (const float*)d_in[11]; p.bhh2 = (const float*)d_in[12];
    const float* w_out = (const float*)d_in[13];
    const float* b_out = (const float*)d_in[14];
    float* out = (float*)d_out;

    const size_t smem_bytes =
        (size_t)(KMAX * NC + 32 * AST + NWIN * CPB + 32) * sizeof(float);  // ~178 KB

    cudaFuncSetAttribute(lstm_all, cudaFuncAttributeMaxDynamicSharedMemorySize,
                         (int)smem_bytes);

    lstm_all<<<NB, NT, smem_bytes>>>(p);
    out_proj_kernel<<<NWIN, 256>>>(w_out, b_out);
    mean_kernel<<<1, 256>>>(out);
}

// round 8
// speedup vs baseline: 3.3749x; 2.4562x over previous
#include <cuda_runtime.h>
#include <math.h>
#include <stdint.h>

// ---------------- problem constants ----------------
#define NWIN 200
#define WINL 160
#define HOPL 80
#define INPD 40
#define HID  768
#define NB   128          // persistent blocks, 1/SM, all co-resident
#define NT   512          // threads per block (16 warps)
#define KMAX 1536         // max fused K (HID + HID)
#define CPB  6            // hidden units per block (128*6 = 768)
#define NC   24           // gate columns per block (4 gates * 6 units)
#define AST  232          // a_s row stride (floats). 232%32=8 + XOR swizzle -> conflict-free

// ---------------- persistent device scratch ----------------
__device__ float g_hA[NWIN * HID];
__device__ float g_hB[NWIN * HID];
__device__ float g_hs0[NWIN * WINL * HID];   // layer0 output sequence
__device__ float g_hs1[NWIN * WINL * HID];   // layer1 output sequence
__device__ float g_y[NWIN * 256];
__device__ unsigned g_barcnt = 0;
__device__ unsigned g_bargen = 0;

struct P {
    const float *x;
    const float *wih0, *whh0, *bih0, *bhh0;
    const float *wih1, *whh1, *bih1, *bhh1;
    const float *wih2, *whh2, *bih2, *bhh2;
};

// ---------------- software grid barrier ----------------
__device__ __forceinline__ void grid_bar() {
    __syncthreads();
    if (threadIdx.x == 0) {
        unsigned g = atomicAdd(&g_bargen, 0u);
        __threadfence();
        unsigned old = atomicAdd(&g_barcnt, 1u);
        if (old == gridDim.x - 1) {
            g_barcnt = 0;
            __threadfence();
            atomicAdd(&g_bargen, 1u);
        } else {
            while (atomicAdd(&g_bargen, 0u) == g) __nanosleep(64);
        }
        __threadfence();
    }
    __syncthreads();
}

// ---------------- fast activations ----------------
__device__ __forceinline__ float sigf(float v) { return 1.f / (1.f + __expf(-v)); }
__device__ __forceinline__ float tanhfast(float x) {
    float ax = fabsf(x);
    float e = __expf(-2.f * ax);
    float t = (1.f - e) / (1.f + e);
    return copysignf(t, x);
}

// ---------------- packed f32x2 helpers ----------------
#define FMA2(acc, a, w) \
    asm("fma.rn.f32x2 %0, %1, %2, %0;" : "+l"(acc) : "l"(a), "l"(w))
#define PACK2(dst, lo, hi) \
    asm("mov.b64 %0, {%1, %2};" : "=l"(dst) : "r"(lo), "r"(hi))

// ============================================================
// Persistent kernel: full 3-layer, 160-step LSTM recurrence
// ============================================================
__global__ void __launch_bounds__(NT, 1) lstm_all(P p)
{
    extern __shared__ float sm[];
    float* w_s = sm;                       // [KMAX][NC]  36864 floats (147 KB)
    float* a0  = w_s + KMAX * NC;          // A tile buf 0: [32][AST] (also gate spill)
    float* a1  = a0 + 32 * AST;            // A tile buf 1
    float* c_s = a1 + 32 * AST;            // [1200] cell state (block-local)
    float* b_s = c_s + NWIN * CPB;         // [24] bias

    const int tid = threadIdx.x;
    const int bid = blockIdx.x;
    const int u0  = bid * CPB;

    // compute-thread mapping: 300 threads, each 4 batch rows x 4 gate cols
    const int tm = tid / 6;                // 0..49 row-group (valid when comp)
    const int tc = tid - tm * 6;           // 0..5  col-group
    const int m0 = tm * 4;
    const int c0 = tc * 4;
    const bool comp = (tid < 300);

    // 8 swizzled A-row base offsets: read addr = kk*AST + (m0 ^ (((kk>>2)&7)<<2))
    int abase[8];
#pragma unroll
    for (int j = 0; j < 8; j++) abase[j] = (m0 ^ (j << 2));

    const float* wih[3] = { p.wih0, p.wih1, p.wih2 };
    const float* whh[3] = { p.whh0, p.whh1, p.whh2 };
    const float* bih[3] = { p.bih0, p.bih1, p.bih2 };
    const float* bhh[3] = { p.bhh0, p.bhh1, p.bhh2 };

    for (int l = 0; l < 3; l++) {
        const int in_dim = (l == 0) ? INPD : HID;
        const int Ktot   = HID + in_dim;              // 808 or 1536
        const int nch    = (Ktot + 31) >> 5;          // 26 or 48
        const float* xin = (l == 1) ? g_hs0 : g_hs1;  // layer>=1 input sequence
        float* hsout = (l == 0) ? g_hs0 : ((l == 1) ? g_hs1 : nullptr);

        // ---- weights into smem: w_s[k][c], zero-padded past Ktot ----
        for (int idx = tid; idx < NC * KMAX; idx += NT) {
            int c = idx / KMAX, k = idx - c * KMAX;
            int g = c / CPB, u = c - g * CPB;
            int row = g * HID + u0 + u;
            float v = 0.f;
            if (k < HID) v = whh[l][row * HID + k];
            else { int kk = k - HID; if (kk < in_dim) v = wih[l][row * in_dim + kk]; }
            w_s[k * NC + c] = v;
        }
        if (tid < NC) {
            int g = tid / CPB, u = tid - g * CPB;
            int col = g * HID + u0 + u;
            b_s[tid] = bih[l][col] + bhh[l][col];
        }
        for (int i = tid; i < NWIN * CPB; i += NT) c_s[i] = 0.f;
        for (int i = tid; i < 1200; i += NT) g_hA[bid * 1200 + i] = 0.f;
        grid_bar();

        for (int t = 0; t < WINL; t++) {
            const float* hcur = (t & 1) ? g_hB : g_hA;
            float*       hnxt = (t & 1) ? g_hA : g_hB;

            float4 r[4];

            // ---------- prefetch helper (macro to keep regs local) ----------
#define PREFETCH(CH)                                                          \
            {                                                                 \
                const int k0_ = (CH) << 5;                                    \
                _Pragma("unroll")                                             \
                for (int j = 0; j < 4; j++) {                                 \
                    int i4 = tid + j * NT;                                    \
                    if (i4 < 1600) {                                          \
                        int m = i4 >> 3, q = i4 & 7;                          \
                        int kg = k0_ + q * 4;                                 \
                        float4 v = make_float4(0.f, 0.f, 0.f, 0.f);           \
                        if (kg < HID)                                         \
                            v = __ldcg((const float4*)(hcur + m * HID + kg)); \
                        else if (kg < Ktot) {                                 \
                            if (l > 0)                                        \
                                v = __ldcg((const float4*)(xin + (m * WINL + t) * HID + (kg - HID))); \
                            else                                              \
                                v = __ldcg((const float4*)(p.x + (m * HOPL + t) * INPD + (kg - HID))); \
                        }                                                     \
                        r[j] = v;                                             \
                    }                                                         \
                }                                                             \
            }

#define COMMIT(BUF)                                                           \
            {                                                                 \
                float* ab_ = (BUF);                                           \
                _Pragma("unroll")                                             \
                for (int j = 0; j < 4; j++) {                                 \
                    int i4 = tid + j * NT;                                    \
                    if (i4 < 1600) {                                          \
                        int m = i4 >> 3, q = i4 & 7;                          \
                        int mx = m ^ (q << 2);                                \
                        ab_[(q * 4 + 0) * AST + mx] = r[j].x;                 \
                        ab_[(q * 4 + 1) * AST + mx] = r[j].y;                 \
                        ab_[(q * 4 + 2) * AST + mx] = r[j].z;                 \
                        ab_[(q * 4 + 3) * AST + mx] = r[j].w;                 \
                    }                                                         \
                }                                                             \
            }

            // stage chunk 0
            PREFETCH(0);
            COMMIT(a0);

            // accumulators: 2 row-pairs x 4 cols, init with bias in both lanes
            unsigned long long acc[2][4];
            if (comp) {
#pragma unroll
                for (int c = 0; c < 4; c++) {
                    unsigned bb = __float_as_uint(b_s[c0 + c]);
                    unsigned long long bp; PACK2(bp, bb, bb);
                    acc[0][c] = bp; acc[1][c] = bp;
                }
            }
            __syncthreads();

            for (int ch = 0; ch < nch; ch++) {
                if (ch + 1 < nch) PREFETCH(ch + 1);       // LDGs in flight over compute

                const float* ab = (ch & 1) ? a1 : a0;
                if (comp) {
                    const float* wrow = w_s + (ch << 5) * NC + c0;
#pragma unroll
                    for (int kk = 0; kk < 32; kk++) {
                        const ulonglong2 av = *reinterpret_cast<const ulonglong2*>(
                            ab + kk * AST + abase[(kk >> 2) & 7]);
                        const float4 wv = *reinterpret_cast<const float4*>(wrow + kk * NC);
                        unsigned long long w0, w1, w2, w3;
                        PACK2(w0, __float_as_uint(wv.x), __float_as_uint(wv.x));
                        PACK2(w1, __float_as_uint(wv.y), __float_as_uint(wv.y));
                        PACK2(w2, __float_as_uint(wv.z), __float_as_uint(wv.z));
                        PACK2(w3, __float_as_uint(wv.w), __float_as_uint(wv.w));
                        FMA2(acc[0][0], av.x, w0); FMA2(acc[1][0], av.y, w0);
                        FMA2(acc[0][1], av.x, w1); FMA2(acc[1][1], av.y, w1);
                        FMA2(acc[0][2], av.x, w2); FMA2(acc[1][2], av.y, w2);
                        FMA2(acc[0][3], av.x, w3); FMA2(acc[1][3], av.y, w3);
                    }
                }

                if (ch + 1 < nch) COMMIT(((ch + 1) & 1) ? a1 : a0);
                __syncthreads();
            }
#undef PREFETCH
#undef COMMIT

            // ---- spill gates (column-major) into a0: gs[c][m], c=gate*6+u ----
            if (comp) {
#pragma unroll
                for (int c = 0; c < 4; c++) {
                    ulonglong2 v; v.x = acc[0][c]; v.y = acc[1][c];
                    *reinterpret_cast<ulonglong2*>(a0 + (c0 + c) * AST + m0) = v;
                }
            }
            __syncthreads();

            // ---- cell update: this block's 6 units x 200 rows ----
            for (int i = tid; i < NWIN * CPB; i += NT) {
                int m = i / 6, u = i - m * 6;
                float gi = a0[(u     ) * AST + m];
                float gf = a0[(6  + u) * AST + m];
                float gg = a0[(12 + u) * AST + m];
                float go = a0[(18 + u) * AST + m];
                float c = c_s[i];
                c = sigf(gf) * c + sigf(gi) * tanhfast(gg);
                float h = sigf(go) * tanhfast(c);
                c_s[i] = c;
                hnxt[m * HID + u0 + u] = h;
                if (hsout) hsout[(m * WINL + t) * HID + u0 + u] = h;
            }
            grid_bar();
        }
        // 160 steps (even count) -> final h of this layer is in g_hA
    }
}

// ---------------- output projection + row normalize ----------------
__global__ void out_proj_kernel(const float* __restrict__ w_out,
                                const float* __restrict__ b_out)
{
    __shared__ float red[256];
    int b = blockIdx.x;
    int o = threadIdx.x;
    const float4* h = (const float4*)(g_hA + (long)b * HID);
    const float4* w = (const float4*)(w_out + (long)o * HID);
    float s = 0.f;
#pragma unroll 4
    for (int k = 0; k < HID / 4; k++) {
        float4 hv = h[k];
        float4 wv = w[k];
        s += hv.x * wv.x + hv.y * wv.y + hv.z * wv.z + hv.w * wv.w;
    }
    float y = s + b_out[o];
    red[o] = y * y;
    __syncthreads();
    for (int st = 128; st > 0; st >>= 1) {
        if (o < st) red[o] += red[o + st];
        __syncthreads();
    }
    float inv = rsqrtf(red[0]);
    g_y[b * 256 + o] = y * inv;
}

__global__ void mean_kernel(float* __restrict__ out) {
    int o = threadIdx.x;
    float s = 0.f;
    for (int b = 0; b < NWIN; b++) s += g_y[b * 256 + o];
    out[o] = s / (float)NWIN;
}

// ---------------- launch ----------------
extern "C" void kernel_launch(void* const* d_in, const int* in_sizes, int n_in,
                              void* d_out, int out_size)
{
    (void)in_sizes; (void)n_in; (void)out_size;
    P p;
    p.x    = (const float*)d_in[0];
    p.wih0 = (const float*)d_in[1];  p.whh0 = (const float*)d_in[2];
    p.bih0 = (const float*)d_in[3];  p.bhh0 = (const float*)d_in[4];
    p.wih1 = (const float*)d_in[5];  p.whh1 = (const float*)d_in[6];
    p.bih1 = (const float*)d_in[7];  p.bhh1 = (const float*)d_in[8];
    p.wih2 = (const float*)d_in[9];  p.whh2 = (const float*)d_in[10];
    p.bih2 = (const float*)d_in[11]; p.bhh2 = (const float*)d_in[12];
    const float* w_out = (const float*)d_in[13];
    const float* b_out = (const float*)d_in[14];
    float* out = (float*)d_out;

    const size_t smem_bytes =
        (size_t)(KMAX * NC + 2 * 32 * AST + NWIN * CPB + 32) * sizeof(float); // ~212 KB

    cudaFuncSetAttribute(lstm_all, cudaFuncAttributeMaxDynamicSharedMemorySize,
                         (int)smem_bytes);

    lstm_all<<<NB, NT, smem_bytes>>>(p);
    out_proj_kernel<<<NWIN, 256>>>(w_out, b_out);
    mean_kernel<<<1, 256>>>(out);
}

// round 10
// speedup vs baseline: 3.3766x; 1.0005x over previous
#include <cuda_runtime.h>
#include <math.h>
#include <stdint.h>

// ---------------- problem constants ----------------
#define NWIN 200
#define WINL 160
#define HOPL 80
#define INPD 40
#define HID  768
#define NB   128          // persistent blocks, 1/SM, all co-resident
#define NT   512          // threads per block (16 warps)
#define KMAX 1536         // max fused K (HID + HID)
#define CPB  6            // hidden units per block (128*6 = 768)
#define NC   24           // gate columns per block (4 gates * 6 units)
#define AST  232          // a_s row stride (floats). 232%32=8 + XOR swizzle -> conflict-free

// ---------------- persistent device scratch ----------------
__device__ float g_hA[NWIN * HID];
__device__ float g_hB[NWIN * HID];
__device__ float g_hs0[NWIN * WINL * HID];   // layer0 output sequence
__device__ float g_hs1[NWIN * WINL * HID];   // layer1 output sequence
__device__ float g_y[NWIN * 256];
__device__ unsigned g_barcnt = 0;
__device__ unsigned g_bargen = 0;

struct P {
    const float *x;
    const float *wih0, *whh0, *bih0, *bhh0;
    const float *wih1, *whh1, *bih1, *bhh1;
    const float *wih2, *whh2, *bih2, *bhh2;
};

// ---------------- software grid barrier ----------------
__device__ __forceinline__ void grid_bar() {
    __syncthreads();
    if (threadIdx.x == 0) {
        unsigned g = atomicAdd(&g_bargen, 0u);
        __threadfence();
        unsigned old = atomicAdd(&g_barcnt, 1u);
        if (old == gridDim.x - 1) {
            g_barcnt = 0;
            __threadfence();
            atomicAdd(&g_bargen, 1u);
        } else {
            while (atomicAdd(&g_bargen, 0u) == g) __nanosleep(64);
        }
        __threadfence();
    }
    __syncthreads();
}

// ---------------- fast activations ----------------
__device__ __forceinline__ float sigf(float v) { return 1.f / (1.f + __expf(-v)); }
__device__ __forceinline__ float tanhfast(float x) {
    float ax = fabsf(x);
    float e = __expf(-2.f * ax);
    float t = (1.f - e) / (1.f + e);
    return copysignf(t, x);
}

// ---------------- packed f32x2 helpers ----------------
#define FMA2(acc, a, w) \
    asm("fma.rn.f32x2 %0, %1, %2, %0;" : "+l"(acc) : "l"(a), "l"(w))
#define PACK2(dst, lo, hi) \
    asm("mov.b64 %0, {%1, %2};" : "=l"(dst) : "r"(lo), "r"(hi))

// ============================================================
// Persistent kernel: full 3-layer, 160-step LSTM recurrence
// ============================================================
__global__ void __launch_bounds__(NT, 1) lstm_all(P p)
{
    extern __shared__ float sm[];
    float* w_s = sm;                       // [KMAX][NC]  36864 floats (147 KB)
    float* a0  = w_s + KMAX * NC;          // A tile buf 0: [32][AST] (also gate spill)
    float* a1  = a0 + 32 * AST;            // A tile buf 1
    float* c_s = a1 + 32 * AST;            // [1200] cell state (block-local)
    float* b_s = c_s + NWIN * CPB;         // [24] bias

    const int tid = threadIdx.x;
    const int bid = blockIdx.x;
    const int u0  = bid * CPB;

    // compute-thread mapping: 300 threads, each 4 batch rows x 4 gate cols
    const int tm = tid / 6;                // 0..49 row-group (valid when comp)
    const int tc = tid - tm * 6;           // 0..5  col-group
    const int m0 = tm * 4;
    const int c0 = tc * 4;
    const bool comp = (tid < 300);

    // 8 swizzled A-row base offsets: read addr = kk*AST + (m0 ^ (((kk>>2)&7)<<2))
    int abase[8];
#pragma unroll
    for (int j = 0; j < 8; j++) abase[j] = (m0 ^ (j << 2));

    const float* wih[3] = { p.wih0, p.wih1, p.wih2 };
    const float* whh[3] = { p.whh0, p.whh1, p.whh2 };
    const float* bih[3] = { p.bih0, p.bih1, p.bih2 };
    const float* bhh[3] = { p.bhh0, p.bhh1, p.bhh2 };

    for (int l = 0; l < 3; l++) {
        const int in_dim = (l == 0) ? INPD : HID;
        const int Ktot   = HID + in_dim;              // 808 or 1536
        const int nch    = (Ktot + 31) >> 5;          // 26 or 48
        const float* xin = (l == 1) ? g_hs0 : g_hs1;  // layer>=1 input sequence
        float* hsout = (l == 0) ? g_hs0 : ((l == 1) ? g_hs1 : nullptr);

        // ---- weights into smem: w_s[k][c], zero-padded past Ktot ----
        for (int idx = tid; idx < NC * KMAX; idx += NT) {
            int c = idx / KMAX, k = idx - c * KMAX;
            int g = c / CPB, u = c - g * CPB;
            int row = g * HID + u0 + u;
            float v = 0.f;
            if (k < HID) v = whh[l][row * HID + k];
            else { int kk = k - HID; if (kk < in_dim) v = wih[l][row * in_dim + kk]; }
            w_s[k * NC + c] = v;
        }
        if (tid < NC) {
            int g = tid / CPB, u = tid - g * CPB;
            int col = g * HID + u0 + u;
            b_s[tid] = bih[l][col] + bhh[l][col];
        }
        for (int i = tid; i < NWIN * CPB; i += NT) c_s[i] = 0.f;
        for (int i = tid; i < 1200; i += NT) g_hA[bid * 1200 + i] = 0.f;
        grid_bar();

        for (int t = 0; t < WINL; t++) {
            const float* hcur = (t & 1) ? g_hB : g_hA;
            float*       hnxt = (t & 1) ? g_hA : g_hB;

            float4 r[4];

            // ---------- prefetch helper (macro to keep regs local) ----------
#define PREFETCH(CH)                                                          \
            {                                                                 \
                const int k0_ = (CH) << 5;                                    \
                _Pragma("unroll")                                             \
                for (int j = 0; j < 4; j++) {                                 \
                    int i4 = tid + j * NT;                                    \
                    if (i4 < 1600) {                                          \
                        int m = i4 >> 3, q = i4 & 7;                          \
                        int kg = k0_ + q * 4;                                 \
                        float4 v = make_float4(0.f, 0.f, 0.f, 0.f);           \
                        if (kg < HID)                                         \
                            v = __ldcg((const float4*)(hcur + m * HID + kg)); \
                        else if (kg < Ktot) {                                 \
                            if (l > 0)                                        \
                                v = __ldcg((const float4*)(xin + (m * WINL + t) * HID + (kg - HID))); \
                            else                                              \
                                v = __ldcg((const float4*)(p.x + (m * HOPL + t) * INPD + (kg - HID))); \
                        }                                                     \
                        r[j] = v;                                             \
                    }                                                         \
                }                                                             \
            }

#define COMMIT(BUF)                                                           \
            {                                                                 \
                float* ab_ = (BUF);                                           \
                _Pragma("unroll")                                             \
                for (int j = 0; j < 4; j++) {                                 \
                    int i4 = tid + j * NT;                                    \
                    if (i4 < 1600) {                                          \
                        int m = i4 >> 3, q = i4 & 7;                          \
                        int mx = m ^ (q << 2);                                \
                        ab_[(q * 4 + 0) * AST + mx] = r[j].x;                 \
                        ab_[(q * 4 + 1) * AST + mx] = r[j].y;                 \
                        ab_[(q * 4 + 2) * AST + mx] = r[j].z;                 \
                        ab_[(q * 4 + 3) * AST + mx] = r[j].w;                 \
                    }                                                         \
                }                                                             \
            }

            // stage chunk 0
            PREFETCH(0);
            COMMIT(a0);

            // accumulators: 2 row-pairs x 4 cols, init with bias in both lanes
            unsigned long long acc[2][4];
            if (comp) {
#pragma unroll
                for (int c = 0; c < 4; c++) {
                    unsigned bb = __float_as_uint(b_s[c0 + c]);
                    unsigned long long bp; PACK2(bp, bb, bb);
                    acc[0][c] = bp; acc[1][c] = bp;
                }
            }
            __syncthreads();

            for (int ch = 0; ch < nch; ch++) {
                if (ch + 1 < nch) PREFETCH(ch + 1);       // LDGs in flight over compute

                const float* ab = (ch & 1) ? a1 : a0;
                if (comp) {
                    const float* wrow = w_s + (ch << 5) * NC + c0;
#pragma unroll
                    for (int kk = 0; kk < 32; kk++) {
                        const ulonglong2 av = *reinterpret_cast<const ulonglong2*>(
                            ab + kk * AST + abase[(kk >> 2) & 7]);
                        const float4 wv = *reinterpret_cast<const float4*>(wrow + kk * NC);
                        unsigned long long w0, w1, w2, w3;
                        PACK2(w0, __float_as_uint(wv.x), __float_as_uint(wv.x));
                        PACK2(w1, __float_as_uint(wv.y), __float_as_uint(wv.y));
                        PACK2(w2, __float_as_uint(wv.z), __float_as_uint(wv.z));
                        PACK2(w3, __float_as_uint(wv.w), __float_as_uint(wv.w));
                        FMA2(acc[0][0], av.x, w0); FMA2(acc[1][0], av.y, w0);
                        FMA2(acc[0][1], av.x, w1); FMA2(acc[1][1], av.y, w1);
                        FMA2(acc[0][2], av.x, w2); FMA2(acc[1][2], av.y, w2);
                        FMA2(acc[0][3], av.x, w3); FMA2(acc[1][3], av.y, w3);
                    }
                }

                if (ch + 1 < nch) COMMIT(((ch + 1) & 1) ? a1 : a0);
                __syncthreads();
            }
#undef PREFETCH
#undef COMMIT

            // ---- spill gates (column-major) into a0: gs[c][m], c=gate*6+u ----
            if (comp) {
#pragma unroll
                for (int c = 0; c < 4; c++) {
                    ulonglong2 v; v.x = acc[0][c]; v.y = acc[1][c];
                    *reinterpret_cast<ulonglong2*>(a0 + (c0 + c) * AST + m0) = v;
                }
            }
            __syncthreads();

            // ---- cell update: this block's 6 units x 200 rows ----
            for (int i = tid; i < NWIN * CPB; i += NT) {
                int m = i / 6, u = i - m * 6;
                float gi = a0[(u     ) * AST + m];
                float gf = a0[(6  + u) * AST + m];
                float gg = a0[(12 + u) * AST + m];
                float go = a0[(18 + u) * AST + m];
                float c = c_s[i];
                c = sigf(gf) * c + sigf(gi) * tanhfast(gg);
                float h = sigf(go) * tanhfast(c);
                c_s[i] = c;
                hnxt[m * HID + u0 + u] = h;
                if (hsout) hsout[(m * WINL + t) * HID + u0 + u] = h;
            }
            grid_bar();
        }
        // 160 steps (even count) -> final h of this layer is in g_hA
    }
}

// ---------------- output projection + row normalize ----------------
__global__ void out_proj_kernel(const float* __restrict__ w_out,
                                const float* __restrict__ b_out)
{
    __shared__ float red[256];
    int b = blockIdx.x;
    int o = threadIdx.x;
    const float4* h = (const float4*)(g_hA + (long)b * HID);
    const float4* w = (const float4*)(w_out + (long)o * HID);
    float s = 0.f;
#pragma unroll 4
    for (int k = 0; k < HID / 4; k++) {
        float4 hv = h[k];
        float4 wv = w[k];
        s += hv.x * wv.x + hv.y * wv.y + hv.z * wv.z + hv.w * wv.w;
    }
    float y = s + b_out[o];
    red[o] = y * y;
    __syncthreads();
    for (int st = 128; st > 0; st >>= 1) {
        if (o < st) red[o] += red[o + st];
        __syncthreads();
    }
    float inv = rsqrtf(red[0]);
    g_y[b * 256 + o] = y * inv;
}

__global__ void mean_kernel(float* __restrict__ out) {
    int o = threadIdx.x;
    float s = 0.f;
    for (int b = 0; b < NWIN; b++) s += g_y[b * 256 + o];
    out[o] = s / (float)NWIN;
}

// ---------------- launch ----------------
extern "C" void kernel_launch(void* const* d_in, const int* in_sizes, int n_in,
                              void* d_out, int out_size)
{
    (void)in_sizes; (void)n_in; (void)out_size;
    P p;
    p.x    = (const float*)d_in[0];
    p.wih0 = (const float*)d_in[1];  p.whh0 = (const float*)d_in[2];
    p.bih0 = (const float*)d_in[3];  p.bhh0 = (const float*)d_in[4];
    p.wih1 = (const float*)d_in[5];  p.whh1 = (const float*)d_in[6];
    p.bih1 = (const float*)d_in[7];  p.bhh1 = (const float*)d_in[8];
    p.wih2 = (const float*)d_in[9];  p.whh2 = (const float*)d_in[10];
    p.bih2 = (const float*)d_in[11]; p.bhh2 = (const float*)d_in[12];
    const float* w_out = (const float*)d_in[13];
    const float* b_out = (const float*)d_in[14];
    float* out = (float*)d_out;

    const size_t smem_bytes =
        (size_t)(KMAX * NC + 2 * 32 * AST + NWIN * CPB + 32) * sizeof(float); // ~212 KB

    cudaFuncSetAttribute(lstm_all, cudaFuncAttributeMaxDynamicSharedMemorySize,
                         (int)smem_bytes);

    lstm_all<<<NB, NT, smem_bytes>>>(p);
    out_proj_kernel<<<NWIN, 256>>>(w_out, b_out);
    mean_kernel<<<1, 256>>>(out);
}

// round 13
// speedup vs baseline: 7.9569x; 2.3565x over previous
#include <cuda_runtime.h>
#include <cuda_bf16.h>
#include <math.h>
#include <stdint.h>

// ---------------- problem constants ----------------
#define NWIN 200
#define WINL 160
#define HOPL 80
#define INPD 40
#define HID  768
#define NB   128
#define NT   512
#define GST  52            // gate spill buffer row stride (floats)

// smem layout (bytes)
#define OFF_BS   0                   // bias: 48 floats
#define OFF_C    192                 // cell state: 1200 floats
#define OFF_A    5120                // A tiles: 2 bufs x (hi 14336 + lo 14336) = 57344
                                     // (post-GEMM aliased as gate buffer 112x52 fp32)
#define OFF_BL   62464               // Wlo: 2 bufs x 6144
#define OFF_BH   74752               // Wh resident: 24 chunks x 48 rows x 128B = 147456
#define SMEM_TOT 222208

// ---------------- persistent device scratch ----------------
__device__ uint32_t g_hPack[2][NWIN * HID];            // packed (lo16<<16 | hi16) bf16 pairs
__device__ uint32_t g_seqPack[2][NWIN * WINL * HID];   // layer0/1 output sequences
__device__ uint32_t g_xPack[NWIN * WINL * INPD + 64];  // windowed input, packed
__device__ __align__(16) __nv_bfloat16 g_wlo[NB * 24 * 3072];  // per-CTA pre-swizzled Wlo
__device__ float g_hF[NWIN * HID];                     // final-layer h (fp32)
__device__ float g_y[NWIN * 256];
__device__ unsigned g_barcnt = 0;
__device__ unsigned g_bargen = 0;

struct P {
    const float *x;
    const float *wih0, *whh0, *bih0, *bhh0;
    const float *wih1, *whh1, *bih1, *bhh1;
    const float *wih2, *whh2, *bih2, *bhh2;
};

// ---------------- helpers ----------------
__device__ __forceinline__ uint32_t smem_u32(const void* p) {
    uint32_t a;
    asm("{ .reg .u64 t; cvta.to.shared.u64 t, %1; cvt.u32.u64 %0, t; }" : "=r"(a) : "l"(p));
    return a;
}
__device__ __forceinline__ void grid_bar() {
    __syncthreads();
    if (threadIdx.x == 0) {
        unsigned g = atomicAdd(&g_bargen, 0u);
        __threadfence();
        unsigned old = atomicAdd(&g_barcnt, 1u);
        if (old == gridDim.x - 1) {
            g_barcnt = 0;
            __threadfence();
            atomicAdd(&g_bargen, 1u);
        } else {
            while (atomicAdd(&g_bargen, 0u) == g) __nanosleep(64);
        }
        __threadfence();
    }
    __syncthreads();
}
__device__ __forceinline__ float sigf(float v) { return 1.f / (1.f + __expf(-v)); }
__device__ __forceinline__ float tanhfast(float x) {
    float ax = fabsf(x);
    float e = __expf(-2.f * ax);
    return copysignf((1.f - e) / (1.f + e), x);
}
__device__ __forceinline__ unsigned sw128(unsigned off) { return off ^ ((off >> 3) & 0x70); }
__device__ __forceinline__ uint32_t packf(float v) {
    __nv_bfloat16 h = __float2bfloat16(v);
    __nv_bfloat16 l = __float2bfloat16(v - __bfloat162float(h));
    return ((uint32_t)__bfloat16_as_ushort(l) << 16) | (uint32_t)__bfloat16_as_ushort(h);
}

// warp-level tensor ops (base-target sm_80+ instructions; work on sm_103)
__device__ __forceinline__ void mma16816(float* d, const uint32_t* a, const uint32_t* b) {
    asm volatile(
        "mma.sync.aligned.m16n8k16.row.col.f32.bf16.bf16.f32 "
        "{%0,%1,%2,%3}, {%4,%5,%6,%7}, {%8,%9}, {%0,%1,%2,%3};"
        : "+f"(d[0]), "+f"(d[1]), "+f"(d[2]), "+f"(d[3])
        : "r"(a[0]), "r"(a[1]), "r"(a[2]), "r"(a[3]), "r"(b[0]), "r"(b[1]));
}
__device__ __forceinline__ void ldsm4(uint32_t* r, uint32_t addr) {
    asm volatile("ldmatrix.sync.aligned.m8n8.x4.shared.b16 {%0,%1,%2,%3}, [%4];"
        : "=r"(r[0]), "=r"(r[1]), "=r"(r[2]), "=r"(r[3]) : "r"(addr));
}
__device__ __forceinline__ void ldsm2(uint32_t* r, uint32_t addr) {
    asm volatile("ldmatrix.sync.aligned.m8n8.x2.shared.b16 {%0,%1}, [%2];"
        : "=r"(r[0]), "=r"(r[1]) : "r"(addr));
}

// ============================================================
// Persistent kernel: full 3-layer, 160-step LSTM recurrence
// ============================================================
__global__ void __launch_bounds__(NT, 1) lstm_all(P p)
{
    extern __shared__ char smc[];
    const uint32_t sb = smem_u32(smc);
    float* b_s  = (float*)(smc + OFF_BS);
    float* c_s  = (float*)(smc + OFF_C);
    float* gbuf = (float*)(smc + OFF_A);     // aliases A buffers (safe: used post-GEMM)

    const int tid  = threadIdx.x;
    const int wid  = tid >> 5;
    const int lane = tid & 31;
    const int bid  = blockIdx.x;
    const int grp  = bid >> 6;               // 0/1 -> rows grp*100 .. +99
    const int nb   = bid & 63;
    const int u0   = nb * 12;                // first hidden unit owned (12 units)
    const bool cw  = (wid < 14);             // compute warps

    // warp tile geometry: m-tile = wid/2 (16 rows), n-half = (wid&1)*24 (3 n-tiles of 8)
    const int m0    = (wid >> 1) * 16;
    const int nhalf = (wid & 1) * 24;

    // ldmatrix lane address geometry (A: rows x k row-major; B: [col][k] row-major)
    const int aRow = m0 + (lane & 15);
    const uint32_t aSwz = (uint32_t)(aRow & 7) << 4;
    const uint32_t aBB  = (uint32_t)aRow * 128 + ((lane & 16) ? 16u : 0u);
    const int bCol = nhalf + (lane & 7) + ((lane & 16) ? 8 : 0);
    const uint32_t bSwz = (uint32_t)(bCol & 7) << 4;
    const uint32_t bBB  = (uint32_t)bCol * 128 + ((lane & 8) ? 16u : 0u);
    const int b2Col = nhalf + 16 + (lane & 7);
    const uint32_t b2Swz = (uint32_t)(b2Col & 7) << 4;
    const uint32_t b2BB  = (uint32_t)b2Col * 128 + ((lane & 8) ? 16u : 0u);

    // ---- precompute windowed, packed input (whole grid cooperates) ----
    for (int idx = bid * NT + tid; idx < NWIN * WINL * INPD; idx += NB * NT) {
        int m = idx / (WINL * INPD);
        int r2 = idx - m * WINL * INPD;
        int tt = r2 / INPD;
        int i = r2 - tt * INPD;
        g_xPack[idx] = packf(__ldcg(&p.x[(m * HOPL + tt) * INPD + i]));
    }
    grid_bar();

    const float* wihA[3] = { p.wih0, p.wih1, p.wih2 };
    const float* whhA[3] = { p.whh0, p.whh1, p.whh2 };
    const float* bihA[3] = { p.bih0, p.bih1, p.bih2 };
    const float* bhhA[3] = { p.bhh0, p.bhh1, p.bhh2 };

    for (int l = 0; l < 3; l++) {
        const int in_dim = (l == 0) ? INPD : HID;
        const int Ktot = HID + in_dim;                 // 808 or 1536
        const int nch = (Ktot + 63) >> 6;              // 13 or 24
        const uint32_t* xsrc = (l == 0) ? g_xPack : g_seqPack[l - 1];
        const long xrs = (l == 0) ? (long)WINL * INPD : (long)WINL * HID;
        const int xw = (l == 0) ? INPD : HID;
        uint32_t* seqOut = (l < 2) ? g_seqPack[l] : nullptr;
        const float* wih = wihA[l];
        const float* whh = whhA[l];

        // ---- weight prep: Wh hi-plane -> smem (resident), Wl lo-plane -> pre-swizzled global ----
        // j = u*4 + g (unit-major gate quadruples); col = g*HID + u0 + u
        for (int idx = tid; idx < 48 * 1536; idx += NT) {
            int j = idx / 1536, k = idx - j * 1536;
            int u = j >> 2, g = j & 3;
            int col = g * HID + u0 + u;
            float v = 0.f;
            if (k < HID) v = whh[col * HID + k];
            else { int kk = k - HID; if (kk < in_dim) v = wih[col * in_dim + kk]; }
            __nv_bfloat16 hi = __float2bfloat16(v);
            __nv_bfloat16 lo = __float2bfloat16(v - __bfloat162float(hi));
            int ch = k >> 6, kk2 = k & 63;
            unsigned sw = sw128((unsigned)(j * 128 + kk2 * 2));
            *(__nv_bfloat16*)(smc + OFF_BH + ch * 6144 + sw) = hi;
            g_wlo[(size_t)(bid * 24 + ch) * 3072 + (sw >> 1)] = lo;
        }
        if (tid < 48) {
            int u = tid >> 2, g = tid & 3;
            int col = g * HID + u0 + u;
            b_s[tid] = bihA[l][col] + bhhA[l][col];
        }
        for (int i = tid; i < 1200; i += NT) c_s[i] = 0.f;
        for (int i = tid; i < 1200; i += NT) g_hPack[0][bid * 1200 + i] = 0u;
        grid_bar();

        for (int t = 0; t < WINL; t++) {
            const uint32_t* hcur = g_hPack[t & 1];
            uint32_t*       hnxt = g_hPack[(t + 1) & 1];

            uint4 vv[4];     // A prefetch regs
            uint4 wl;        // Wlo prefetch reg

#define PREF(CH)                                                               \
            {                                                                  \
                const int k0_ = (CH) << 6;                                     \
                _Pragma("unroll")                                              \
                for (int j = 0; j < 4; j++) {                                  \
                    int idx = tid + j * NT;                                    \
                    if (idx < 1600) {                                          \
                        int r = idx >> 4, q = idx & 15;                        \
                        int m = grp * 100 + r;                                 \
                        int kg = k0_ + q * 4;                                  \
                        uint4 v;                                               \
                        if (kg < HID)                                          \
                            v = __ldcg((const uint4*)(hcur + m * HID + kg));   \
                        else if (kg + 4 <= Ktot)                               \
                            v = __ldcg((const uint4*)(xsrc + (long)m * xrs + (long)t * xw + (kg - HID))); \
                        else v = make_uint4(0, 0, 0, 0);                       \
                        vv[j] = v;                                             \
                    }                                                          \
                }                                                              \
                if (tid < 384)                                                 \
                    wl = __ldcg(((const uint4*)(g_wlo + (size_t)(bid * 24 + (CH)) * 3072)) + tid); \
            }

#define COMMITA(ABUF, BLBUF)                                                   \
            {                                                                  \
                _Pragma("unroll")                                              \
                for (int j = 0; j < 4; j++) {                                  \
                    int idx = tid + j * NT;                                    \
                    if (idx < 1600) {                                          \
                        int r = idx >> 4, q = idx & 15;                        \
                        uint4 v = vv[j];                                       \
                        uint32_t h01 = __byte_perm(v.x, v.y, 0x5410);          \
                        uint32_t h23 = __byte_perm(v.z, v.w, 0x5410);          \
                        uint32_t l01 = __byte_perm(v.x, v.y, 0x7632);          \
                        uint32_t l23 = __byte_perm(v.z, v.w, 0x7632);          \
                        unsigned off = sw128((unsigned)(r * 128 + q * 8));     \
                        *(uint2*)(smc + (ABUF) + off) = make_uint2(h01, h23);  \
                        *(uint2*)(smc + (ABUF) + 14336 + off) = make_uint2(l01, l23); \
                    }                                                          \
                }                                                              \
                if (tid < 384) *(((uint4*)(smc + (BLBUF))) + tid) = wl;        \
            }

            // stage chunk 0 into buffer 0
            PREF(0);
            COMMITA(OFF_A, OFF_BL);

            float acc[3][4];
            if (cw) {
#pragma unroll
                for (int nt = 0; nt < 3; nt++)
#pragma unroll
                    for (int q = 0; q < 4; q++) acc[nt][q] = 0.f;
            }
            __syncthreads();

            for (int ch = 0; ch < nch; ch++) {
                if (ch + 1 < nch) PREF(ch + 1);

                if (cw) {
                    const uint32_t aB  = sb + OFF_A + (uint32_t)(ch & 1) * 28672u;
                    const uint32_t bhB = sb + OFF_BH + (uint32_t)ch * 6144u;
                    const uint32_t blB = sb + OFF_BL + (uint32_t)(ch & 1) * 6144u;
#pragma unroll
                    for (int ks = 0; ks < 4; ks++) {
                        uint32_t ah[4], al[4], bh[6], bl[6];
                        uint32_t ao = (aBB + (uint32_t)ks * 32u) ^ aSwz;
                        ldsm4(ah, aB + ao);
                        ldsm4(al, aB + 14336u + ao);
                        uint32_t bo  = (bBB  + (uint32_t)ks * 32u) ^ bSwz;
                        uint32_t b2o = (b2BB + (uint32_t)ks * 32u) ^ b2Swz;
                        ldsm4(bh, bhB + bo);
                        ldsm2(bh + 4, bhB + b2o);
                        ldsm4(bl, blB + bo);
                        ldsm2(bl + 4, blB + b2o);
#pragma unroll
                        for (int nt = 0; nt < 3; nt++) {
                            mma16816(acc[nt], ah, bh + 2 * nt);   // Ah*Bh
                            mma16816(acc[nt], al, bh + 2 * nt);   // Al*Bh
                            mma16816(acc[nt], ah, bl + 2 * nt);   // Ah*Bl
                        }
                    }
                }

                if (ch + 1 < nch)
                    COMMITA(OFF_A + ((ch + 1) & 1) * 28672, OFF_BL + ((ch + 1) & 1) * 6144);
                __syncthreads();
            }
#undef PREF
#undef COMMITA

            // ---- spill gate accumulators to gbuf[row][col] (aliases A bufs, GEMM done) ----
            if (cw) {
                int r0 = m0 + (lane >> 2);
#pragma unroll
                for (int nt = 0; nt < 3; nt++) {
                    int cn = nhalf + nt * 8 + (lane & 3) * 2;
                    *(float2*)&gbuf[r0 * GST + cn]       = make_float2(acc[nt][0], acc[nt][1]);
                    *(float2*)&gbuf[(r0 + 8) * GST + cn] = make_float2(acc[nt][2], acc[nt][3]);
                }
            }
            __syncthreads();

            // ---- cell update: 100 rows x 12 units, block-local ----
            for (int i = tid; i < 1200; i += NT) {
                int row = i / 12, u = i - row * 12;
                float gi = gbuf[row * GST + u * 4 + 0] + b_s[u * 4 + 0];
                float gf = gbuf[row * GST + u * 4 + 1] + b_s[u * 4 + 1];
                float gg = gbuf[row * GST + u * 4 + 2] + b_s[u * 4 + 2];
                float go = gbuf[row * GST + u * 4 + 3] + b_s[u * 4 + 3];
                float c = c_s[i];
                c = sigf(gf) * c + sigf(gi) * tanhfast(gg);
                float h = sigf(go) * tanhfast(c);
                c_s[i] = c;
                int m = grp * 100 + row;
                uint32_t pk = packf(h);
                hnxt[m * HID + u0 + u] = pk;
                if (seqOut) seqOut[(size_t)(m * WINL + t) * HID + u0 + u] = pk;
                else if (t == WINL - 1) g_hF[m * HID + u0 + u] = h;
            }
            grid_bar();
        }
    }
}

// ---------------- output projection + row normalize ----------------
__global__ void out_proj_kernel(const float* __restrict__ w_out,
                                const float* __restrict__ b_out)
{
    __shared__ float red[256];
    int b = blockIdx.x;
    int o = threadIdx.x;
    const float4* h = (const float4*)(g_hF + (long)b * HID);
    const float4* w = (const float4*)(w_out + (long)o * HID);
    float s = 0.f;
#pragma unroll 4
    for (int k = 0; k < HID / 4; k++) {
        float4 hv = h[k];
        float4 wv = w[k];
        s += hv.x * wv.x + hv.y * wv.y + hv.z * wv.z + hv.w * wv.w;
    }
    float y = s + b_out[o];
    red[o] = y * y;
    __syncthreads();
    for (int st = 128; st > 0; st >>= 1) {
        if (o < st) red[o] += red[o + st];
        __syncthreads();
    }
    float inv = rsqrtf(red[0]);
    g_y[b * 256 + o] = y * inv;
}

__global__ void mean_kernel(float* __restrict__ out) {
    int o = threadIdx.x;
    float s = 0.f;
    for (int b = 0; b < NWIN; b++) s += g_y[b * 256 + o];
    out[o] = s / (float)NWIN;
}

// ---------------- launch ----------------
extern "C" void kernel_launch(void* const* d_in, const int* in_sizes, int n_in,
                              void* d_out, int out_size)
{
    (void)in_sizes; (void)n_in; (void)out_size;
    P p;
    p.x    = (const float*)d_in[0];
    p.wih0 = (const float*)d_in[1];  p.whh0 = (const float*)d_in[2];
    p.bih0 = (const float*)d_in[3];  p.bhh0 = (const float*)d_in[4];
    p.wih1 = (const float*)d_in[5];  p.whh1 = (const float*)d_in[6];
    p.bih1 = (const float*)d_in[7];  p.bhh1 = (const float*)d_in[8];
    p.wih2 = (const float*)d_in[9];  p.whh2 = (const float*)d_in[10];
    p.bih2 = (const float*)d_in[11]; p.bhh2 = (const float*)d_in[12];
    const float* w_out = (const float*)d_in[13];
    const float* b_out = (const float*)d_in[14];
    float* out = (float*)d_out;

    cudaFuncSetAttribute(lstm_all, cudaFuncAttributeMaxDynamicSharedMemorySize, SMEM_TOT);

    lstm_all<<<NB, NT, SMEM_TOT>>>(p);
    out_proj_kernel<<<NWIN, 256>>>(w_out, b_out);
    mean_kernel<<<1, 256>>>(out);
}

// round 15
// speedup vs baseline: 8.0207x; 1.0080x over previous
#include <cuda_runtime.h>
#include <cuda_bf16.h>
#include <math.h>
#include <stdint.h>

// ---------------- problem constants ----------------
#define NWIN 200
#define WINL 160
#define HOPL 80
#define INPD 40
#define HID  768
#define NB   128
#define NT   512
#define NCT  224           // compute threads (7 warps)
#define NST  288           // staging threads (9 warps)

// smem layout (bytes)
#define OFF_BS   0                   // bias: 48 floats
#define OFF_A    1024                // A ring: 2 slots x (hi 14336 + lo 14336) = 57344
#define OFF_BL   58368               // Wlo ring: 2 slots x 6144
#define OFF_BH   70656               // Wh resident: 24 chunks x 48 rows x 128B = 147456
#define SMEM_TOT 218112

// named barrier ids (0 reserved for __syncthreads)
#define FULL0 1
#define FULL1 2
#define EMPT0 3
#define EMPT1 4
#define HDONE 5
#define GBARS 6

#define BAR_SYNC(id, cnt)   asm volatile("bar.sync %0, %1;"   :: "r"(id), "r"(cnt) : "memory")
#define BAR_ARRIVE(id, cnt) asm volatile("bar.arrive %0, %1;" :: "r"(id), "r"(cnt) : "memory")

// ---------------- persistent device scratch ----------------
__device__ uint32_t g_hPack[2][NWIN * HID];            // packed (lo16<<16 | hi16) bf16 pairs
__device__ uint32_t g_seqPack[2][NWIN * WINL * HID];   // layer0/1 output sequences
__device__ uint32_t g_xPack[NWIN * WINL * INPD + 64];  // windowed input, packed
__device__ __align__(16) __nv_bfloat16 g_wlo[NB * 24 * 3072];  // per-CTA pre-swizzled Wlo
__device__ float g_hF[NWIN * HID];                     // final-layer h (fp32)
__device__ float g_y[NWIN * 256];
__device__ unsigned g_barcnt = 0;
__device__ unsigned g_bargen = 0;

struct P {
    const float *x;
    const float *wih0, *whh0, *bih0, *bhh0;
    const float *wih1, *whh1, *bih1, *bhh1;
    const float *wih2, *whh2, *bih2, *bhh2;
};

// ---------------- helpers ----------------
__device__ __forceinline__ uint32_t smem_u32(const void* p) {
    uint32_t a;
    asm("{ .reg .u64 t; cvta.to.shared.u64 t, %1; cvt.u32.u64 %0, t; }" : "=r"(a) : "l"(p));
    return a;
}
__device__ __forceinline__ void grid_bar() {          // all-thread layer-level barrier
    __syncthreads();
    if (threadIdx.x == 0) {
        unsigned g = atomicAdd(&g_bargen, 0u);
        __threadfence();
        unsigned old = atomicAdd(&g_barcnt, 1u);
        if (old == gridDim.x - 1) {
            g_barcnt = 0;
            __threadfence();
            atomicAdd(&g_bargen, 1u);
        } else {
            while (atomicAdd(&g_bargen, 0u) == g) __nanosleep(64);
        }
        __threadfence();
    }
    __syncthreads();
}
__device__ __forceinline__ float sigf(float v) { return 1.f / (1.f + __expf(-v)); }
__device__ __forceinline__ float tanhfast(float x) {
    float ax = fabsf(x);
    float e = __expf(-2.f * ax);
    return copysignf((1.f - e) / (1.f + e), x);
}
__device__ __forceinline__ unsigned sw128(unsigned off) { return off ^ ((off >> 3) & 0x70); }
__device__ __forceinline__ uint32_t packf(float v) {
    __nv_bfloat16 h = __float2bfloat16(v);
    __nv_bfloat16 l = __float2bfloat16(v - __bfloat162float(h));
    return ((uint32_t)__bfloat16_as_ushort(l) << 16) | (uint32_t)__bfloat16_as_ushort(h);
}
__device__ __forceinline__ void mma16816(float* d, const uint32_t* a, const uint32_t* b) {
    asm volatile(
        "mma.sync.aligned.m16n8k16.row.col.f32.bf16.bf16.f32 "
        "{%0,%1,%2,%3}, {%4,%5,%6,%7}, {%8,%9}, {%0,%1,%2,%3};"
        : "+f"(d[0]), "+f"(d[1]), "+f"(d[2]), "+f"(d[3])
        : "r"(a[0]), "r"(a[1]), "r"(a[2]), "r"(a[3]), "r"(b[0]), "r"(b[1]));
}
__device__ __forceinline__ void ldsm4(uint32_t* r, uint32_t addr) {
    asm volatile("ldmatrix.sync.aligned.m8n8.x4.shared.b16 {%0,%1,%2,%3}, [%4];"
        : "=r"(r[0]), "=r"(r[1]), "=r"(r[2]), "=r"(r[3]) : "r"(addr));
}

// ============================================================
// Persistent kernel: full 3-layer, 160-step LSTM recurrence
// ============================================================
__global__ void __launch_bounds__(NT, 1) lstm_all(P p)
{
    extern __shared__ char smc[];
    const uint32_t sb = smem_u32(smc);
    float* b_s = (float*)(smc + OFF_BS);

    const int tid  = threadIdx.x;
    const int wid  = tid >> 5;
    const int lane = tid & 31;
    const int bid  = blockIdx.x;
    const int grp  = bid >> 6;               // rows grp*100 .. +99
    const int nb   = bid & 63;
    const int u0   = nb * 12;                // 12 hidden units owned
    const bool isC = (tid < NCT);            // compute warps 0-6
    const int stid = tid - NCT;              // staging thread id (valid if !isC)

    // compute-warp ldmatrix geometry (m-tile = wid; B spans all 48 cols)
    const int aRow = wid * 16 + (lane & 15);
    const uint32_t aSwz = (uint32_t)(aRow & 7) << 4;
    const uint32_t aBB  = (uint32_t)aRow * 128 + ((lane & 16) ? 16u : 0u);
    const uint32_t colRel = (uint32_t)((lane & 7) + ((lane & 16) ? 8 : 0));
    const uint32_t bSwzL  = (uint32_t)(lane & 7) << 4;
    const uint32_t bKofs  = (lane & 8) ? 16u : 0u;

    // zero the whole A ring once: pad rows (100..111) stay zero forever
    for (int i = tid * 16; i < 57344; i += NT * 16)
        *(uint4*)(smc + OFF_A + i) = make_uint4(0, 0, 0, 0);

    // precompute windowed, packed input (whole grid)
    for (int idx = bid * NT + tid; idx < NWIN * WINL * INPD; idx += NB * NT) {
        int m = idx / (WINL * INPD);
        int r2 = idx - m * WINL * INPD;
        int tt = r2 / INPD;
        int i = r2 - tt * INPD;
        g_xPack[idx] = packf(__ldcg(&p.x[(m * HOPL + tt) * INPD + i]));
    }
    grid_bar();

    const float* wihA[3] = { p.wih0, p.wih1, p.wih2 };
    const float* whhA[3] = { p.whh0, p.whh1, p.whh2 };
    const float* bihA[3] = { p.bih0, p.bih1, p.bih2 };
    const float* bhhA[3] = { p.bhh0, p.bhh1, p.bhh2 };

    unsigned cnt = 0;                         // chunk ring cursor (both groups track)

    for (int l = 0; l < 3; l++) {
        const int in_dim = (l == 0) ? INPD : HID;
        const int Ktot = HID + in_dim;
        const int nch = (Ktot + 63) >> 6;     // 13 or 24
        const uint32_t* xsrc = (l == 0) ? g_xPack : g_seqPack[l - 1];
        const long xrs = (l == 0) ? (long)WINL * INPD : (long)WINL * HID;
        const int xw = (l == 0) ? INPD : HID;
        uint32_t* seqOut = (l < 2) ? g_seqPack[l] : nullptr;
        const float* wih = wihA[l];
        const float* whh = whhA[l];

        // ---- weight prep (all threads): Wh hi -> smem resident, Wlo -> pre-swizzled global ----
        for (int idx = tid; idx < 48 * 1536; idx += NT) {
            int j = idx / 1536, k = idx - j * 1536;
            int u = j >> 2, g = j & 3;
            int col = g * HID + u0 + u;
            float v = 0.f;
            if (k < HID) v = whh[col * HID + k];
            else { int kk = k - HID; if (kk < in_dim) v = wih[col * in_dim + kk]; }
            __nv_bfloat16 hi = __float2bfloat16(v);
            __nv_bfloat16 lo = __float2bfloat16(v - __bfloat162float(hi));
            int ch = k >> 6, kk2 = k & 63;
            unsigned sw = sw128((unsigned)(j * 128 + kk2 * 2));
            *(__nv_bfloat16*)(smc + OFF_BH + ch * 6144 + sw) = hi;
            g_wlo[(size_t)(bid * 24 + ch) * 3072 + (sw >> 1)] = lo;
        }
        if (tid < 48) {
            int u = tid >> 2, g = tid & 3;
            int col = g * HID + u0 + u;
            b_s[tid] = bihA[l][col] + bhhA[l][col];
        }
        for (int i = tid; i < 1200; i += NT) g_hPack[0][bid * 1200 + i] = 0u;
        grid_bar();

        if (!isC) {
            // =============== PRODUCER warps (9): stage A + Wlo chunks ===============
            for (int t = 0; t < WINL; t++) {
                if (t > 0) {
                    BAR_SYNC(HDONE, NT);                 // wait local epilogue of t-1
                    if (stid == 0) {                     // inter-CTA h barrier
                        unsigned g = atomicAdd(&g_bargen, 0u);
                        __threadfence();
                        unsigned old = atomicAdd(&g_barcnt, 1u);
                        if (old == gridDim.x - 1) {
                            g_barcnt = 0;
                            __threadfence();
                            atomicAdd(&g_bargen, 1u);
                        } else {
                            while (atomicAdd(&g_bargen, 0u) == g) __nanosleep(64);
                        }
                        __threadfence();
                    }
                    BAR_SYNC(GBARS, NST);
                }
                const uint32_t* hcur = g_hPack[t & 1];
                for (int ch = 0; ch < nch; ch++) {
                    int s = cnt & 1;
                    if (cnt >= 2) BAR_SYNC(EMPT0 + s, NT);
                    const int k0 = ch << 6;
                    uint4 vv[6];
#pragma unroll
                    for (int j = 0; j < 6; j++) {
                        int idx = stid + j * NST;
                        uint4 v = make_uint4(0, 0, 0, 0);
                        if (idx < 1600) {
                            int r = idx >> 4, q = idx & 15;
                            int m = grp * 100 + r;
                            int kg = k0 + q * 4;
                            if (kg < HID)
                                v = __ldcg((const uint4*)(hcur + m * HID + kg));
                            else if (kg + 4 <= Ktot)
                                v = __ldcg((const uint4*)(xsrc + (long)m * xrs + (long)t * xw + (kg - HID)));
                        }
                        vv[j] = v;
                    }
                    const uint4* wsrc = (const uint4*)(g_wlo + (size_t)(bid * 24 + ch) * 3072);
                    uint4 wl0 = __ldcg(wsrc + stid);
                    uint4 wl1;
                    bool w1v = (stid + NST) < 384;
                    if (w1v) wl1 = __ldcg(wsrc + stid + NST);

                    char* ab = smc + OFF_A + s * 28672;
#pragma unroll
                    for (int j = 0; j < 6; j++) {
                        int idx = stid + j * NST;
                        if (idx < 1600) {
                            int r = idx >> 4, q = idx & 15;
                            uint4 v = vv[j];
                            uint32_t h01 = __byte_perm(v.x, v.y, 0x5410);
                            uint32_t h23 = __byte_perm(v.z, v.w, 0x5410);
                            uint32_t l01 = __byte_perm(v.x, v.y, 0x7632);
                            uint32_t l23 = __byte_perm(v.z, v.w, 0x7632);
                            unsigned off = sw128((unsigned)(r * 128 + q * 8));
                            *(uint2*)(ab + off) = make_uint2(h01, h23);
                            *(uint2*)(ab + 14336 + off) = make_uint2(l01, l23);
                        }
                    }
                    *((uint4*)(smc + OFF_BL + s * 6144) + stid) = wl0;
                    if (w1v) *((uint4*)(smc + OFF_BL + s * 6144) + stid + NST) = wl1;
                    __threadfence_block();
                    BAR_ARRIVE(FULL0 + s, NT);
                    cnt++;
                }
            }
        } else {
            // =============== COMPUTE warps (7): MMA + epilogue ===============
            float creg[6];
#pragma unroll
            for (int i = 0; i < 6; i++) creg[i] = 0.f;
            const int gL = lane & 3;
            const int rLo = lane >> 2;
            const bool evenL = ((gL & 1) == 0);

            for (int t = 0; t < WINL; t++) {
                uint32_t* hnxt = g_hPack[(t + 1) & 1];

                float acc[6][4];
#pragma unroll
                for (int nt = 0; nt < 6; nt++) {
                    float bA = b_s[8 * nt + 2 * gL];
                    float bB = b_s[8 * nt + 2 * gL + 1];
                    acc[nt][0] = bA; acc[nt][1] = bB;
                    acc[nt][2] = bA; acc[nt][3] = bB;
                }

                for (int ch = 0; ch < nch; ch++) {
                    int s = cnt & 1;
                    BAR_SYNC(FULL0 + s, NT);
                    const uint32_t aB  = sb + OFF_A + (uint32_t)s * 28672u;
                    const uint32_t blB = sb + OFF_BL + (uint32_t)s * 6144u;
                    const uint32_t bhB = sb + OFF_BH + (uint32_t)ch * 6144u;
#pragma unroll
                    for (int ks = 0; ks < 4; ks++) {
                        uint32_t ah[4], al[4];
                        uint32_t ao = (aBB + (uint32_t)ks * 32u) ^ aSwz;
                        ldsm4(ah, aB + ao);
                        ldsm4(al, aB + 14336u + ao);
#pragma unroll
                        for (int g = 0; g < 3; g++) {
                            uint32_t bh[4], bl[4];
                            uint32_t bo = (((uint32_t)(g * 16) + colRel) * 128u + bKofs
                                           + (uint32_t)ks * 32u) ^ bSwzL;
                            ldsm4(bh, bhB + bo);
                            ldsm4(bl, blB + bo);
                            mma16816(acc[2 * g],     ah, bh);
                            mma16816(acc[2 * g],     al, bh);
                            mma16816(acc[2 * g],     ah, bl);
                            mma16816(acc[2 * g + 1], ah, bh + 2);
                            mma16816(acc[2 * g + 1], al, bh + 2);
                            mma16816(acc[2 * g + 1], ah, bl + 2);
                        }
                    }
                    BAR_ARRIVE(EMPT0 + s, NT);
                    cnt++;
                }

                // ---- epilogue: lane exchange + cell update, all in registers ----
#pragma unroll
                for (int nt = 0; nt < 6; nt++) {
                    float o0 = __shfl_xor_sync(0xffffffffu, acc[nt][0], 1);
                    float o1 = __shfl_xor_sync(0xffffffffu, acc[nt][1], 1);
                    float o2 = __shfl_xor_sync(0xffffffffu, acc[nt][2], 1);
                    float o3 = __shfl_xor_sync(0xffffffffu, acc[nt][3], 1);
                    float gi, gf, gg, go;
                    int row;
                    if (evenL) { gi = acc[nt][0]; gf = acc[nt][1]; gg = o0; go = o1; row = rLo; }
                    else       { gi = o2; gf = o3; gg = acc[nt][2]; go = acc[nt][3]; row = rLo + 8; }
                    float c = creg[nt];
                    c = sigf(gf) * c + sigf(gi) * tanhfast(gg);
                    float h = sigf(go) * tanhfast(c);
                    creg[nt] = c;
                    int mrow = wid * 16 + row;
                    if (mrow < 100) {
                        int u = 2 * nt + (gL >> 1);
                        int m = grp * 100 + mrow;
                        uint32_t pk = packf(h);
                        hnxt[m * HID + u0 + u] = pk;
                        if (seqOut) seqOut[(size_t)(m * WINL + t) * HID + u0 + u] = pk;
                        else if (t == WINL - 1) g_hF[m * HID + u0 + u] = h;
                    }
                }
                __threadfence();
                if (t != WINL - 1) BAR_ARRIVE(HDONE, NT);
                // reset cell state at layer end handled by creg re-init next layer
            }
#pragma unroll
            for (int i = 0; i < 6; i++) creg[i] = 0.f;   // (dead store; clarity)
        }
        // layer boundary: both groups fall through; next grid_bar in prep syncs everyone
    }
}

// ---------------- output projection + row normalize ----------------
__global__ void out_proj_kernel(const float* __restrict__ w_out,
                                const float* __restrict__ b_out)
{
    __shared__ float red[256];
    int b = blockIdx.x;
    int o = threadIdx.x;
    const float4* h = (const float4*)(g_hF + (long)b * HID);
    const float4* w = (const float4*)(w_out + (long)o * HID);
    float s = 0.f;
#pragma unroll 4
    for (int k = 0; k < HID / 4; k++) {
        float4 hv = h[k];
        float4 wv = w[k];
        s += hv.x * wv.x + hv.y * wv.y + hv.z * wv.z + hv.w * wv.w;
    }
    float y = s + b_out[o];
    red[o] = y * y;
    __syncthreads();
    for (int st = 128; st > 0; st >>= 1) {
        if (o < st) red[o] += red[o + st];
        __syncthreads();
    }
    float inv = rsqrtf(red[0]);
    g_y[b * 256 + o] = y * inv;
}

__global__ void mean_kernel(float* __restrict__ out) {
    int o = threadIdx.x;
    float s = 0.f;
    for (int b = 0; b < NWIN; b++) s += g_y[b * 256 + o];
    out[o] = s / (float)NWIN;
}

// ---------------- launch ----------------
extern "C" void kernel_launch(void* const* d_in, const int* in_sizes, int n_in,
                              void* d_out, int out_size)
{
    (void)in_sizes; (void)n_in; (void)out_size;
    P p;
    p.x    = (const float*)d_in[0];
    p.wih0 = (const float*)d_in[1];  p.whh0 = (const float*)d_in[2];
    p.bih0 = (const float*)d_in[3];  p.bhh0 = (const float*)d_in[4];
    p.wih1 = (const float*)d_in[5];  p.whh1 = (const float*)d_in[6];
    p.bih1 = (const float*)d_in[7];  p.bhh1 = (const float*)d_in[8];
    p.wih2 = (const float*)d_in[9];  p.whh2 = (const float*)d_in[10];
    p.bih2 = (const float*)d_in[11]; p.bhh2 = (const float*)d_in[12];
    const float* w_out = (const float*)d_in[13];
    const float* b_out = (const float*)d_in[14];
    float* out = (float*)d_out;

    cudaFuncSetAttribute(lstm_all, cudaFuncAttributeMaxDynamicSharedMemorySize, SMEM_TOT);

    lstm_all<<<NB, NT, SMEM_TOT>>>(p);
    out_proj_kernel<<<NWIN, 256>>>(w_out, b_out);
    mean_kernel<<<1, 256>>>(out);
}